// round 3
// baseline (speedup 1.0000x reference)
#include <cuda_runtime.h>
#include <cuda_bf16.h>

#define TT 8
#define G  16
#define GG 256
#define DD 64
#define SB 9      // uint4 stride of a bf16 row (8 data + 1 pad) -> conflict-free
#define SR 20     // float4 stride of an rmx row (permuted layout) -> conflict-free
#define THRS 0.5f

// 0 wl, 1 pool, 2 obj, 3 pres, 4 flowsq, 5 sumzp, 6 sumflow
__device__ double g_acc[8];
__device__ unsigned g_ctr;

__device__ __forceinline__ float wsum(float v) {
#pragma unroll
    for (int s = 16; s > 0; s >>= 1) v += __shfl_xor_sync(0xffffffffu, v, s);
    return v;
}

// bf16x2 pack/unpack: bf16 is the top 16 bits of fp32.
__device__ __forceinline__ unsigned pk2(float e0, float e1) {
    unsigned r;
    asm("cvt.rn.bf16x2.f32 %0, %1, %2;" : "=r"(r) : "f"(e1), "f"(e0));
    return r;  // e0 in low half, e1 in high half
}
__device__ __forceinline__ float blo(unsigned u)  { return __uint_as_float(u << 16); }
__device__ __forceinline__ float bhi(unsigned u)  { return __uint_as_float(u & 0xFFFF0000u); }
__device__ __forceinline__ float balo(unsigned u) { return __uint_as_float((u << 16) & 0x7FFF0000u); }
__device__ __forceinline__ float bahi(unsigned u) { return __uint_as_float(u & 0x7FFF0000u); }

// One block per (t,t+1,b) pair; 1024 threads = 4 threads per cell (D split).
__global__ __launch_bounds__(1024, 1) void main_kernel(const float* __restrict__ zw,
                                                       const float* __restrict__ zp,
                                                       int B) {
    extern __shared__ char smraw[];
    uint4*  s0b = (uint4*)smraw;            // frame t, bf16  [GG][SB]
    uint4*  s1b = s0b + GG * SB;            // frame t+1, bf16
    float4* rmx = (float4*)(s1b + GG * SB); // col-max of |s0|*p0, fp32 [GG][SR]
    float*  p0s = (float*)(rmx + GG * SR);
    float*  p1s = p0s + GG;
    float*  n1s = p1s + GG;
    __shared__ double rd[3];

    int pair = blockIdx.x;
    int b = pair % B, t = pair / B;
    int tid = threadIdx.x;
    size_t f0 = (size_t)(t * B + b);
    size_t f1 = f0 + B;
    const float4* g0 = (const float4*)(zw + f0 * (GG * DD));
    const float4* g1 = (const float4*)(zw + f1 * (GG * DD));

    if (tid < GG) {
        p0s[tid] = zp[f0 * GG + tid];
        p1s[tid] = zp[f1 * GG + tid];
    }
    if (tid < 3) rd[tid] = 0.0;

    // ---- coalesced load: exact fp32 z_what_loss + bf16 frames into smem ----
    float wl = 0.f;
#pragma unroll
    for (int it = 0; it < 4; ++it) {
        int idx = it * 1024 + tid;
        float4 a = g0[idx];
        float4 c4 = g1[idx];
        float dx = c4.x - a.x, dy = c4.y - a.y, dz = c4.z - a.z, dw = c4.w - a.w;
        wl += dx * dx + dy * dy + dz * dz + dw * dw;
        int row = idx >> 4, d4 = idx & 15;
        uint2 pa, pb;
        pa.x = pk2(a.x, a.y);  pa.y = pk2(a.z, a.w);
        pb.x = pk2(c4.x, c4.y); pb.y = pk2(c4.z, c4.w);
        ((uint2*)(s0b + row * SB))[d4] = pa;
        ((uint2*)(s1b + row * SB))[d4] = pb;
    }
    __syncthreads();

    int c = tid >> 2, dq = tid & 3;
    int i = c >> 4, j = c & 15;

    // ---- separable maxpool pass: col-max of |s0|*p0 -> rmx (fp32, permuted) ----
    {
        int cm = (j > 0)  ? c - 1 : c;
        int cp = (j < 15) ? c + 1 : c;
        float pzm = (j > 0)  ? p0s[cm] : 0.f;
        float pz0 = p0s[c];
        float pzp = (j < 15) ? p0s[cp] : 0.f;
#pragma unroll
        for (int it = 0; it < 2; ++it) {
            uint4 um = s0b[cm * SB + dq * 2 + it];
            uint4 u0 = s0b[c  * SB + dq * 2 + it];
            uint4 up = s0b[cp * SB + dq * 2 + it];
            float m[8];
            const unsigned* wm = (const unsigned*)&um;
            const unsigned* w0 = (const unsigned*)&u0;
            const unsigned* wp = (const unsigned*)&up;
#pragma unroll
            for (int q = 0; q < 4; ++q) {
                m[q * 2 + 0] = fmaxf(fmaxf(balo(wm[q]) * pzm, balo(w0[q]) * pz0), balo(wp[q]) * pzp);
                m[q * 2 + 1] = fmaxf(fmaxf(bahi(wm[q]) * pzm, bahi(w0[q]) * pz0), bahi(wp[q]) * pzp);
            }
            // logical float4 q = 4*dq + 2*it + h  ->  physical slot (2*it+h)*4 + dq
            rmx[c * SR + (2 * it + 0) * 4 + dq] = make_float4(m[0], m[1], m[2], m[3]);
            rmx[c * SR + (2 * it + 1) * 4 + dq] = make_float4(m[4], m[5], m[6], m[7]);
        }
    }
    __syncthreads();

    // ---- 9 wrapped neighbors (frame t+1) + pres mask ----
    int nidx[9];
    unsigned pmask = 0;
    {
        int k = 0;
#pragma unroll
        for (int di = -1; di <= 1; ++di)
#pragma unroll
            for (int dj = -1; dj <= 1; ++dj, ++k) {
                int nc = ((i + di) & 15) * 16 + ((j + dj) & 15);
                nidx[k] = nc;
                if (p1s[nc] > THRS) pmask |= (1u << k);
            }
    }
    int ru  = (i > 0)  ? c - 16 : c;  // duplicate row when clamped: max unchanged
    int rdn = (i < 15) ? c + 16 : c;
    float p0c = p0s[c], p1c = p1s[c];

    float dot[9] = {0.f, 0.f, 0.f, 0.f, 0.f, 0.f, 0.f, 0.f, 0.f};
    float pn = 0.f, cn = 0.f, pd = 0.f, na = 0.f;

#pragma unroll
    for (int it = 0; it < 2; ++it) {
        uint4 pu = s0b[c * SB + dq * 2 + it];
        const unsigned* pw = (const unsigned*)&pu;
        float pr[8];
#pragma unroll
        for (int q = 0; q < 4; ++q) { pr[q * 2] = blo(pw[q]); pr[q * 2 + 1] = bhi(pw[q]); }
#pragma unroll
        for (int e = 0; e < 8; ++e) pn += pr[e] * pr[e];

        float actr[8];
#pragma unroll
        for (int k = 0; k < 9; ++k) {
            uint4 nu = s1b[nidx[k] * SB + dq * 2 + it];
            const unsigned* nw = (const unsigned*)&nu;
            float d = dot[k];
#pragma unroll
            for (int q = 0; q < 4; ++q) {
                float v0 = blo(nw[q]), v1 = bhi(nw[q]);
                d += pr[q * 2] * v0;
                d += pr[q * 2 + 1] * v1;
                if (k == 4) { actr[q * 2] = fabsf(v0); actr[q * 2 + 1] = fabsf(v1); }
            }
            dot[k] = d;
        }
#pragma unroll
        for (int e = 0; e < 8; ++e) cn += actr[e] * actr[e];

#pragma unroll
        for (int h = 0; h < 2; ++h) {
            int slot = (2 * it + h) * 4 + dq;
            float4 mu = rmx[ru  * SR + slot];
            float4 mc = rmx[c   * SR + slot];
            float4 md = rmx[rdn * SR + slot];
            float4 m;
            m.x = fmaxf(fmaxf(mu.x, mc.x), md.x);
            m.y = fmaxf(fmaxf(mu.y, mc.y), md.y);
            m.z = fmaxf(fmaxf(mu.z, mc.z), md.z);
            m.w = fmaxf(fmaxf(mu.w, mc.w), md.w);
            pd += m.x * actr[h * 4 + 0] + m.y * actr[h * 4 + 1]
                + m.z * actr[h * 4 + 2] + m.w * actr[h * 4 + 3];
            na += m.x * m.x + m.y * m.y + m.z * m.z + m.w * m.w;
        }
    }

    // combine the 4 D-partials of each cell (lanes dq=0..3 are adjacent)
#pragma unroll
    for (int s = 1; s <= 2; s <<= 1) {
#pragma unroll
        for (int q = 0; q < 9; ++q) dot[q] += __shfl_xor_sync(0xffffffffu, dot[q], s);
        pn += __shfl_xor_sync(0xffffffffu, pn, s);
        cn += __shfl_xor_sync(0xffffffffu, cn, s);
        pd += __shfl_xor_sync(0xffffffffu, pd, s);
        na += __shfl_xor_sync(0xffffffffu, na, s);
    }
    if (dq == 0) n1s[c] = cn;
    __syncthreads();

    float obj = 0.f, pool = 0.f;
    if (dq == 0) {
        float prior_n = fmaxf(sqrtf(pn), 1e-8f);
        float ssum = 0.f, smax = -INFINITY;
#pragma unroll
        for (int k = 0; k < 9; ++k) {
            float nn = fmaxf(sqrtf(n1s[nidx[k]]), 1e-8f);
            float s = __fdividef(dot[k], prior_n * nn);
            if (pmask & (1u << k)) {
                ssum += s;
                smax = fmaxf(smax, s);
            }
        }
        if (p0c > THRS && pmask) obj = -5.0f * smax + ssum;
        float nb = fmaxf(p1c * sqrtf(cn), 1e-6f);
        float cosp = __fdividef(pd * p1c, fmaxf(sqrtf(na), 1e-6f) * nb);
        pool = -cosp * 0.5f * (p0c + p1c);
    }

    wl = wsum(wl); pool = wsum(pool); obj = wsum(obj);
    if ((tid & 31) == 0) {
        atomicAdd(&rd[0], (double)wl);
        atomicAdd(&rd[1], (double)pool);
        atomicAdd(&rd[2], (double)obj);
    }
    __syncthreads();
    if (tid == 0) {
        atomicAdd(&g_acc[0], rd[0]);
        atomicAdd(&g_acc[1], rd[1]);
        atomicAdd(&g_acc[2], rd[2]);
    }
}

// 128 blocks x multiple images each: pres triples, flow term, global sums.
// Last block finalizes the loss and resets the accumulators.
__global__ __launch_bounds__(256) void pf_kernel(const float* __restrict__ zp,
                                                 const float* __restrict__ fl,
                                                 const void* __restrict__ gs,
                                                 float* __restrict__ out,
                                                 int B, int ipb) {
    __shared__ float sp[2][GG];
    __shared__ double rd[4];
    __shared__ unsigned isLast;
    int c = threadIdx.x;
    int i = c >> 4, j = c & 15;
    int nimg = TT * B;
    if (c < 4) rd[c] = 0.0;

    float a_fsq = 0.f, a_zp = 0.f, a_fl = 0.f, a_pres = 0.f;

    for (int q = 0; q < ipb; ++q) {
        int n = blockIdx.x * ipb + q;
        if (n >= nimg) break;
        int t = n / B, b = n % B;
        int buf = q & 1;

        float zpc = zp[(size_t)n * GG + c];
        sp[buf][c] = zpc;
        __syncthreads();

        float mx = -INFINITY;
#pragma unroll
        for (int di = -1; di <= 1; ++di) {
            int ii = i + di;
            if (ii < 0 || ii >= G) continue;
#pragma unroll
            for (int dj = -1; dj <= 1; ++dj) {
                int jj = j + dj;
                if (jj < 0 || jj >= G) continue;
                mx = fmaxf(mx, sp[buf][ii * G + jj]);
            }
        }

        float f = fl[(size_t)n * GG + c];
        a_fsq += (f > 0.5f) ? (mx - f) * (mx - f) : 0.f;
        a_zp  += zpc;
        a_fl  += f;

        if (t >= 1 && t <= TT - 2) {
            float za = zp[(size_t)(n - B) * GG + c];
            float zb = zp[(size_t)(n + B) * GG + c];
            float dba = zb - za;
            float sim = 1.f - dba * dba;
            float d1 = zb - zpc, d2 = za - zpc;
            a_pres += sim * (d1 * d1 + d2 * d2);
        }
        // next iter writes the other buffer; its read is fenced by that sync
    }

    float v0 = wsum(a_fsq), v1 = wsum(a_zp), v2 = wsum(a_fl), v3 = wsum(a_pres);
    if ((c & 31) == 0) {
        atomicAdd(&rd[0], (double)v0);
        atomicAdd(&rd[1], (double)v1);
        atomicAdd(&rd[2], (double)v2);
        atomicAdd(&rd[3], (double)v3);
    }
    __syncthreads();
    if (c == 0) {
        atomicAdd(&g_acc[4], rd[0]);
        atomicAdd(&g_acc[5], rd[1]);
        atomicAdd(&g_acc[6], rd[2]);
        atomicAdd(&g_acc[3], rd[3]);
        __threadfence();
        unsigned old = atomicAdd(&g_ctr, 1u);
        isLast = (old == gridDim.x - 1) ? 1u : 0u;
    }
    __syncthreads();

    if (isLast && c == 0) {
        __threadfence();
        volatile double* ga = g_acc;
        int gi = *(const int*)gs;
        double gstep;
        if (gi < 0 || gi > 1000000000) gstep = (double)__int_as_float(gi);
        else gstep = (double)gi;

        double scale_obj = gstep / 200000.0;   if (scale_obj > 1.0) scale_obj = 1.0;
        double scale_flow = 1.0 - gstep / 100000.0;  if (scale_flow < 0.0) scale_flow = 0.0;

        double hinge = ga[5] - ga[6];
        if (hinge < 0.0) hinge = 0.0;
        double flow_loss = ga[4] + 100.0 * hinge;

        double loss = ga[0]                        // z_what_loss (ADJ_W=1)
                    + ga[3]                        // z_pres_loss (PRES_W=1)
                    + ga[1]                        // pool (POOL_W=1)
                    + ga[2] * scale_obj * 10.0     // objects * OBJ_W
                    + flow_loss * scale_flow;      // FLOW_W=1
        out[0] = (float)loss;

#pragma unroll
        for (int q = 0; q < 8; ++q) g_acc[q] = 0.0;
        g_ctr = 0u;
    }
}

extern "C" void kernel_launch(void* const* d_in, const int* in_sizes, int n_in,
                              void* d_out, int out_size) {
    const float* zw = (const float*)d_in[0];
    const float* zp = (const float*)d_in[1];
    const float* fl = (const float*)d_in[2];
    const void*  gs = d_in[3];
    int B = in_sizes[0] / (TT * GG * DD);

    const int SMEM_BYTES = 2 * GG * SB * 16 + GG * SR * 16 + 3 * GG * 4;  // 158,720 B
    static int configured = 0;
    if (!configured) {
        cudaFuncSetAttribute(main_kernel, cudaFuncAttributeMaxDynamicSharedMemorySize, SMEM_BYTES);
        configured = 1;
    }

    int nimg = TT * B;
    int pfgrid = 128;
    int ipb = (nimg + pfgrid - 1) / pfgrid;

    main_kernel<<<(TT - 1) * B, 1024, SMEM_BYTES>>>(zw, zp, B);
    pf_kernel<<<pfgrid, 256>>>(zp, fl, gs, (float*)d_out, B, ipb);
}

// round 4
// speedup vs baseline: 1.7964x; 1.7964x over previous
#include <cuda_runtime.h>
#include <cuda_bf16.h>

#define TT 8
#define G  16
#define GG 256
#define DD 64
#define SB 9      // uint4 stride of a bf16 row (8 data + 1 pad) -> conflict-free
#define THRS 0.5f

// slot-spread accumulators: 0 wl, 1 pool, 2 obj, 3 pres, 4 flowsq, 5 sumzp, 6 sumflow
__device__ double g_slot[7][16];
__device__ unsigned g_ctr;

__device__ __forceinline__ float wsum(float v) {
#pragma unroll
    for (int s = 16; s > 0; s >>= 1) v += __shfl_xor_sync(0xffffffffu, v, s);
    return v;
}

// bf16 pack/unpack (bf16 = top 16 bits of fp32)
__device__ __forceinline__ unsigned pk2(float e0, float e1) {
    unsigned r;
    asm("cvt.rn.bf16x2.f32 %0, %1, %2;" : "=r"(r) : "f"(e1), "f"(e0));
    return r;  // e0 low half, e1 high half
}
__device__ __forceinline__ float blo(unsigned u)  { return __uint_as_float(u << 16); }
__device__ __forceinline__ float bhi(unsigned u)  { return __uint_as_float(u & 0xFFFF0000u); }
__device__ __forceinline__ float balo(unsigned u) { return __uint_as_float((u << 16) & 0x7FFF0000u); }
__device__ __forceinline__ float bahi(unsigned u) { return __uint_as_float(u & 0x7FFF0000u); }
__device__ __forceinline__ float fmax3(float a, float b, float c) { return fmaxf(fmaxf(a, b), c); }

#define SMEM_BYTES (3 * GG * SB * 16 + 3 * GG * 4)  // 113,664 B -> 2 blocks/SM

// Merged kernel: blocks [0, npair) = pair blocks (thread = cell),
// blocks [npair, npair+nimg) = per-image pres/flow blocks. Last block finalizes.
__global__ __launch_bounds__(256, 2) void fused_kernel(const float* __restrict__ zw,
                                                       const float* __restrict__ zp,
                                                       const float* __restrict__ fl,
                                                       const void* __restrict__ gs,
                                                       float* __restrict__ out,
                                                       int B, int npair, int nimg) {
    extern __shared__ char smraw[];
    __shared__ double rd[4];
    __shared__ unsigned isLast;
    int tid = threadIdx.x;
    int blk = blockIdx.x;
    int slot = blk & 15;
    if (tid < 4) rd[tid] = 0.0;

    if (blk < npair) {
        // ================= pair block: wl / pool / objects =================
        uint4* s0b = (uint4*)smraw;            // frame t   bf16 [GG][SB]
        uint4* s1b = s0b + GG * SB;            // frame t+1 bf16
        uint4* rmxb = s1b + GG * SB;           // col-max of |s0|*p0, bf16
        float* p0s = (float*)(rmxb + GG * SB);
        float* p1s = p0s + GG;
        float* n1s = p1s + GG;

        int b = blk % B, t = blk / B;
        size_t f0 = (size_t)(t * B + b);
        size_t f1 = f0 + B;
        const float4* g0 = (const float4*)(zw + f0 * (GG * DD));
        const float4* g1 = (const float4*)(zw + f1 * (GG * DD));

        p0s[tid] = zp[f0 * GG + tid];
        p1s[tid] = zp[f1 * GG + tid];

        // coalesced load: exact fp32 z_what_loss + bf16 frames into smem
        float wl = 0.f;
#pragma unroll
        for (int it = 0; it < 16; ++it) {
            int idx = it * 256 + tid;
            float4 a = g0[idx];
            float4 v = g1[idx];
            float dx = v.x - a.x, dy = v.y - a.y, dz = v.z - a.z, dw = v.w - a.w;
            wl += dx * dx + dy * dy + dz * dz + dw * dw;
            int row = idx >> 4, d4 = idx & 15;
            uint2 pa, pb;
            pa.x = pk2(a.x, a.y);  pa.y = pk2(a.z, a.w);
            pb.x = pk2(v.x, v.y);  pb.y = pk2(v.z, v.w);
            ((uint2*)(s0b + row * SB))[d4] = pa;
            ((uint2*)(s1b + row * SB))[d4] = pb;
        }
        __syncthreads();

        int c = tid;
        int i = c >> 4, j = c & 15;

        // separable maxpool: column-direction max of |s0|*p0 -> rmxb (bf16)
        {
            int cm = (j > 0)  ? c - 1 : c;
            int cp = (j < 15) ? c + 1 : c;
            float pzm = (j > 0)  ? p0s[cm] : 0.f;
            float pz0 = p0s[c];
            float pzp = (j < 15) ? p0s[cp] : 0.f;
#pragma unroll
            for (int q = 0; q < 8; ++q) {
                uint4 um = s0b[cm * SB + q];
                uint4 u0 = s0b[c  * SB + q];
                uint4 up = s0b[cp * SB + q];
                const unsigned* wm = (const unsigned*)&um;
                const unsigned* w0 = (const unsigned*)&u0;
                const unsigned* wp = (const unsigned*)&up;
                float m[8];
#pragma unroll
                for (int w = 0; w < 4; ++w) {
                    m[2 * w]     = fmax3(balo(wm[w]) * pzm, balo(w0[w]) * pz0, balo(wp[w]) * pzp);
                    m[2 * w + 1] = fmax3(bahi(wm[w]) * pzm, bahi(w0[w]) * pz0, bahi(wp[w]) * pzp);
                }
                uint4 o;
                o.x = pk2(m[0], m[1]); o.y = pk2(m[2], m[3]);
                o.z = pk2(m[4], m[5]); o.w = pk2(m[6], m[7]);
                rmxb[c * SB + q] = o;
            }
        }
        __syncthreads();

        // 9 wrapped neighbors (frame t+1) + pres mask
        int nidx[9];
        unsigned pmask = 0;
        {
            int k = 0;
#pragma unroll
            for (int di = -1; di <= 1; ++di)
#pragma unroll
                for (int dj = -1; dj <= 1; ++dj, ++k) {
                    int nc = ((i + di) & 15) * 16 + ((j + dj) & 15);
                    nidx[k] = nc;
                    if (p1s[nc] > THRS) pmask |= (1u << k);
                }
        }
        int ru  = (i > 0)  ? c - 16 : c;   // duplicated row when clamped: max unchanged
        int rdn = (i < 15) ? c + 16 : c;
        float p0c = p0s[c], p1c = p1s[c];

        float dot[9] = {0.f, 0.f, 0.f, 0.f, 0.f, 0.f, 0.f, 0.f, 0.f};
        float pn = 0.f, cn = 0.f, pd = 0.f, na = 0.f;

#pragma unroll
        for (int q = 0; q < 8; ++q) {
            uint4 pu = s0b[c * SB + q];
            const unsigned* pw = (const unsigned*)&pu;
            float pr[8];
#pragma unroll
            for (int w = 0; w < 4; ++w) { pr[2 * w] = blo(pw[w]); pr[2 * w + 1] = bhi(pw[w]); }
#pragma unroll
            for (int e = 0; e < 8; ++e) pn += pr[e] * pr[e];

            float actr[8];
#pragma unroll
            for (int k = 0; k < 9; ++k) {
                uint4 nu = s1b[nidx[k] * SB + q];
                const unsigned* nw = (const unsigned*)&nu;
                float d = dot[k];
#pragma unroll
                for (int w = 0; w < 4; ++w) {
                    float v0 = blo(nw[w]), v1 = bhi(nw[w]);
                    d += pr[2 * w] * v0;
                    d += pr[2 * w + 1] * v1;
                    if (k == 4) { actr[2 * w] = fabsf(v0); actr[2 * w + 1] = fabsf(v1); }
                }
                dot[k] = d;
            }
#pragma unroll
            for (int e = 0; e < 8; ++e) cn += actr[e] * actr[e];

            uint4 xu = rmxb[ru  * SB + q];
            uint4 xc = rmxb[c   * SB + q];
            uint4 xd = rmxb[rdn * SB + q];
            const unsigned* au = (const unsigned*)&xu;
            const unsigned* ac = (const unsigned*)&xc;
            const unsigned* ad = (const unsigned*)&xd;
#pragma unroll
            for (int w = 0; w < 4; ++w) {
                float m0 = fmax3(blo(au[w]), blo(ac[w]), blo(ad[w]));
                float m1 = fmax3(bhi(au[w]), bhi(ac[w]), bhi(ad[w]));
                pd += m0 * actr[2 * w] + m1 * actr[2 * w + 1];
                na += m0 * m0 + m1 * m1;
            }
        }

        n1s[c] = cn;
        __syncthreads();

        float prior_n = fmaxf(sqrtf(pn), 1e-8f);
        float ssum = 0.f, smax = -INFINITY;
#pragma unroll
        for (int k = 0; k < 9; ++k) {
            float nn = fmaxf(sqrtf(n1s[nidx[k]]), 1e-8f);
            float s = __fdividef(dot[k], prior_n * nn);
            if (pmask & (1u << k)) {
                ssum += s;
                smax = fmaxf(smax, s);
            }
        }
        float obj = (p0c > THRS && pmask) ? (-5.0f * smax + ssum) : 0.f;
        float nb = fmaxf(p1c * sqrtf(cn), 1e-6f);
        float cosp = __fdividef(pd * p1c, fmaxf(sqrtf(na), 1e-6f) * nb);
        float pool = -cosp * 0.5f * (p0c + p1c);

        wl = wsum(wl); pool = wsum(pool); obj = wsum(obj);
        if ((tid & 31) == 0) {
            atomicAdd(&rd[0], (double)wl);
            atomicAdd(&rd[1], (double)pool);
            atomicAdd(&rd[2], (double)obj);
        }
        __syncthreads();
        if (tid == 0) {
            atomicAdd(&g_slot[0][slot], rd[0]);
            atomicAdd(&g_slot[1][slot], rd[1]);
            atomicAdd(&g_slot[2][slot], rd[2]);
        }
    } else {
        // ================= image block: pres triples + flow term =================
        float* sp = (float*)smraw;
        int n = blk - npair;
        int t = n / B, b = n % B;
        int c = tid;

        float zpc = zp[(size_t)n * GG + c];
        sp[c] = zpc;
        __syncthreads();

        int i = c >> 4, j = c & 15;
        float mx = -INFINITY;
#pragma unroll
        for (int di = -1; di <= 1; ++di) {
            int ii = i + di;
            if (ii < 0 || ii >= G) continue;
#pragma unroll
            for (int dj = -1; dj <= 1; ++dj) {
                int jj = j + dj;
                if (jj < 0 || jj >= G) continue;
                mx = fmaxf(mx, sp[ii * G + jj]);
            }
        }

        float f = fl[(size_t)n * GG + c];
        float fsq = (f > 0.5f) ? (mx - f) * (mx - f) : 0.f;

        float pres = 0.f;
        if (t >= 1 && t <= TT - 2) {
            float za = zp[(size_t)(n - B) * GG + c];
            float zb = zp[(size_t)(n + B) * GG + c];
            float dba = zb - za;
            float sim = 1.f - dba * dba;
            float d1 = zb - zpc, d2 = za - zpc;
            pres += sim * (d1 * d1 + d2 * d2);
        }

        float v0 = wsum(fsq), v1 = wsum(zpc), v2 = wsum(f), v3 = wsum(pres);
        if ((c & 31) == 0) {
            atomicAdd(&rd[0], (double)v0);
            atomicAdd(&rd[1], (double)v1);
            atomicAdd(&rd[2], (double)v2);
            atomicAdd(&rd[3], (double)v3);
        }
        __syncthreads();
        if (tid == 0) {
            atomicAdd(&g_slot[4][slot], rd[0]);
            atomicAdd(&g_slot[5][slot], rd[1]);
            atomicAdd(&g_slot[6][slot], rd[2]);
            atomicAdd(&g_slot[3][slot], rd[3]);
        }
    }

    // ================= last-block finalize =================
    if (tid == 0) {
        __threadfence();
        unsigned old = atomicAdd(&g_ctr, 1u);
        isLast = (old == (unsigned)(npair + nimg) - 1u) ? 1u : 0u;
    }
    __syncthreads();

    if (isLast && tid == 0) {
        __threadfence();
        double acc[7];
#pragma unroll
        for (int q = 0; q < 7; ++q) {
            double s = 0.0;
#pragma unroll
            for (int r = 0; r < 16; ++r) { s += g_slot[q][r]; g_slot[q][r] = 0.0; }
            acc[q] = s;
        }
        g_ctr = 0u;

        int gi = *(const int*)gs;
        double gstep = (gi < 0 || gi > 1000000000) ? (double)__int_as_float(gi) : (double)gi;

        double scale_obj = gstep / 200000.0;        if (scale_obj > 1.0) scale_obj = 1.0;
        double scale_flow = 1.0 - gstep / 100000.0; if (scale_flow < 0.0) scale_flow = 0.0;

        double hinge = acc[5] - acc[6];
        if (hinge < 0.0) hinge = 0.0;
        double flow_loss = acc[4] + 100.0 * hinge;

        double loss = acc[0]                        // z_what_loss (ADJ_W=1)
                    + acc[3]                        // z_pres_loss (PRES_W=1)
                    + acc[1]                        // pool (POOL_W=1)
                    + acc[2] * scale_obj * 10.0     // objects * OBJ_W
                    + flow_loss * scale_flow;       // FLOW_W=1
        out[0] = (float)loss;
    }
}

extern "C" void kernel_launch(void* const* d_in, const int* in_sizes, int n_in,
                              void* d_out, int out_size) {
    const float* zw = (const float*)d_in[0];
    const float* zp = (const float*)d_in[1];
    const float* fl = (const float*)d_in[2];
    const void*  gs = d_in[3];
    int B = in_sizes[0] / (TT * GG * DD);

    static int configured = 0;
    if (!configured) {
        cudaFuncSetAttribute(fused_kernel, cudaFuncAttributeMaxDynamicSharedMemorySize, SMEM_BYTES);
        configured = 1;
    }

    int npair = (TT - 1) * B;
    int nimg  = TT * B;
    fused_kernel<<<npair + nimg, 256, SMEM_BYTES>>>(zw, zp, fl, gs, (float*)d_out, B, npair, nimg);
}

// round 5
// speedup vs baseline: 1.7975x; 1.0006x over previous
#include <cuda_runtime.h>
#include <cuda_bf16.h>

#define TT 8
#define G  16
#define GG 256
#define DD 64
#define SB 9      // uint4 stride of a bf16 row (8 data + 1 pad) -> conflict-free
#define THRS 0.5f

// slot-spread accumulators: 0 wl, 1 pool, 2 obj, 3 pres, 4 flowsq, 5 sumzp, 6 sumflow
__device__ double g_slot[7][16];
__device__ unsigned g_ctr;

typedef unsigned long long u64;

__device__ __forceinline__ float wsum(float v) {
#pragma unroll
    for (int s = 16; s > 0; s >>= 1) v += __shfl_xor_sync(0xffffffffu, v, s);
    return v;
}

// ---- packed f32x2 helpers ----
__device__ __forceinline__ u64 mk2(unsigned lo, unsigned hi) {
    u64 r; asm("mov.b64 %0, {%1, %2};" : "=l"(r) : "r"(lo), "r"(hi)); return r;
}
__device__ __forceinline__ u64 mkf(float lo, float hi) {
    u64 r; asm("mov.b64 %0, {%1, %2};" : "=l"(r) : "f"(lo), "f"(hi)); return r;
}
__device__ __forceinline__ u64 ffma2(u64 a, u64 b, u64 c) {
    u64 r; asm("fma.rn.f32x2 %0, %1, %2, %3;" : "=l"(r) : "l"(a), "l"(b), "l"(c)); return r;
}
__device__ __forceinline__ float lohisum(u64 v) {
    unsigned a, b; asm("mov.b64 {%0, %1}, %2;" : "=r"(a), "=r"(b) : "l"(v));
    return __uint_as_float(a) + __uint_as_float(b);
}

// bf16 helpers (bf16 = top 16 bits of fp32)
__device__ __forceinline__ unsigned pk2(float e0, float e1) {
    unsigned r;
    asm("cvt.rn.bf16x2.f32 %0, %1, %2;" : "=r"(r) : "f"(e1), "f"(e0));
    return r;  // e0 low half, e1 high half
}
__device__ __forceinline__ float asf(unsigned u)  { return __uint_as_float(u); }
__device__ __forceinline__ float balo(unsigned u) { return __uint_as_float((u << 16) & 0x7FFF0000u); }
__device__ __forceinline__ float bahi(unsigned u) { return __uint_as_float(u & 0x7FFF0000u); }
__device__ __forceinline__ float fmax3(float a, float b, float c) { return fmaxf(fmaxf(a, b), c); }

#define SMEM_BYTES (3 * GG * SB * 16 + 3 * GG * 4)  // 113,664 B -> 2 blocks/SM

// blocks [0,npair): pair blocks (thread = cell); [npair,npair+nimg): image blocks.
__global__ __launch_bounds__(256, 2) void fused_kernel(const float* __restrict__ zw,
                                                       const float* __restrict__ zp,
                                                       const float* __restrict__ fl,
                                                       const void* __restrict__ gs,
                                                       float* __restrict__ out,
                                                       int B, int npair, int nimg) {
    extern __shared__ char smraw[];
    __shared__ double rd[4];
    __shared__ unsigned isLast;
    int tid = threadIdx.x;
    int blk = blockIdx.x;
    int slot = blk & 15;
    if (tid < 4) rd[tid] = 0.0;

    if (blk < npair) {
        // ================= pair block: wl / pool / objects =================
        uint4* s0b = (uint4*)smraw;            // frame t   bf16 [GG][SB]
        uint4* s1b = s0b + GG * SB;            // frame t+1 bf16
        uint4* rmxb = s1b + GG * SB;           // col-max of |s0|*p0, bf16
        float* p0s = (float*)(rmxb + GG * SB);
        float* p1s = p0s + GG;
        float* n1s = p1s + GG;

        int b = blk % B, t = blk / B;
        size_t f0 = (size_t)(t * B + b);
        size_t f1 = f0 + B;
        const float4* g0 = (const float4*)(zw + f0 * (GG * DD));
        const float4* g1 = (const float4*)(zw + f1 * (GG * DD));

        p0s[tid] = zp[f0 * GG + tid];
        p1s[tid] = zp[f1 * GG + tid];

        // coalesced load: exact fp32 z_what_loss (packed math) + bf16 frames
        const u64 NEG1 = 0xBF800000BF800000ULL;  // {-1.f, -1.f}
        u64 wl2a = 0ULL, wl2b = 0ULL;
#pragma unroll
        for (int it = 0; it < 16; ++it) {
            int idx = it * 256 + tid;
            float4 a = g0[idx];
            float4 v = g1[idx];
            u64 a01 = mkf(a.x, a.y), a23 = mkf(a.z, a.w);
            u64 v01 = mkf(v.x, v.y), v23 = mkf(v.z, v.w);
            u64 d01 = ffma2(a01, NEG1, v01);
            u64 d23 = ffma2(a23, NEG1, v23);
            wl2a = ffma2(d01, d01, wl2a);
            wl2b = ffma2(d23, d23, wl2b);
            int row = idx >> 4, d4 = idx & 15;
            uint2 pa, pb;
            pa.x = pk2(a.x, a.y);  pa.y = pk2(a.z, a.w);
            pb.x = pk2(v.x, v.y);  pb.y = pk2(v.z, v.w);
            ((uint2*)(s0b + row * SB))[d4] = pa;
            ((uint2*)(s1b + row * SB))[d4] = pb;
        }
        float wl = lohisum(wl2a) + lohisum(wl2b);
        __syncthreads();

        int c = tid;
        int i = c >> 4, j = c & 15;

        // separable maxpool: column-direction max of |s0|*p0 -> rmxb (bf16)
        {
            int cm = (j > 0)  ? c - 1 : c;
            int cp = (j < 15) ? c + 1 : c;
            float pzm = (j > 0)  ? p0s[cm] : 0.f;
            float pz0 = p0s[c];
            float pzp = (j < 15) ? p0s[cp] : 0.f;
#pragma unroll
            for (int q = 0; q < 8; ++q) {
                uint4 um = s0b[cm * SB + q];
                uint4 u0 = s0b[c  * SB + q];
                uint4 up = s0b[cp * SB + q];
                const unsigned* wm = (const unsigned*)&um;
                const unsigned* w0 = (const unsigned*)&u0;
                const unsigned* wp = (const unsigned*)&up;
                float m[8];
#pragma unroll
                for (int w = 0; w < 4; ++w) {
                    m[2 * w]     = fmax3(balo(wm[w]) * pzm, balo(w0[w]) * pz0, balo(wp[w]) * pzp);
                    m[2 * w + 1] = fmax3(bahi(wm[w]) * pzm, bahi(w0[w]) * pz0, bahi(wp[w]) * pzp);
                }
                uint4 o;
                o.x = pk2(m[0], m[1]); o.y = pk2(m[2], m[3]);
                o.z = pk2(m[4], m[5]); o.w = pk2(m[6], m[7]);
                rmxb[c * SB + q] = o;
            }
        }
        __syncthreads();

        // 9 wrapped neighbors (frame t+1) + pres mask
        int nidx[9];
        unsigned pmask = 0;
        {
            int k = 0;
#pragma unroll
            for (int di = -1; di <= 1; ++di)
#pragma unroll
                for (int dj = -1; dj <= 1; ++dj, ++k) {
                    int nc = ((i + di) & 15) * 16 + ((j + dj) & 15);
                    nidx[k] = nc;
                    if (p1s[nc] > THRS) pmask |= (1u << k);
                }
        }
        int ru  = (i > 0)  ? c - 16 : c;   // duplicated row when clamped: max unchanged
        int rdn = (i < 15) ? c + 16 : c;
        float p0c = p0s[c], p1c = p1s[c];

        u64 dot2[9];
#pragma unroll
        for (int k = 0; k < 9; ++k) dot2[k] = 0ULL;
        u64 pn2 = 0ULL, cn2 = 0ULL, pd2 = 0ULL, na2 = 0ULL;

#pragma unroll
        for (int q = 0; q < 8; ++q) {
            uint4 pu = s0b[c * SB + q];
            const unsigned* pw = (const unsigned*)&pu;
            u64 pr2[4];
#pragma unroll
            for (int w = 0; w < 4; ++w) {
                pr2[w] = mk2(pw[w] << 16, pw[w] & 0xFFFF0000u);   // exact center pair
                pn2 = ffma2(pr2[w], pr2[w], pn2);
            }

            u64 ctrabs[4];
#pragma unroll
            for (int k = 0; k < 9; ++k) {
                uint4 nu = s1b[nidx[k] * SB + q];
                const unsigned* nw = (const unsigned*)&nu;
#pragma unroll
                for (int w = 0; w < 4; ++w) {
                    // hi half carries <=1 bf16-ulp mantissa junk: benign (see theory)
                    u64 v = mk2(nw[w] << 16, nw[w]);
                    dot2[k] = ffma2(pr2[w], v, dot2[k]);
                    if (k == 4) {
                        ctrabs[w] = mk2((nw[w] << 16) & 0x7FFF0000u, nw[w] & 0x7FFF0000u);
                        cn2 = ffma2(ctrabs[w], ctrabs[w], cn2);
                    }
                }
            }

            uint4 xu = rmxb[ru  * SB + q];
            uint4 xc = rmxb[c   * SB + q];
            uint4 xd = rmxb[rdn * SB + q];
            const unsigned* au = (const unsigned*)&xu;
            const unsigned* ac = (const unsigned*)&xc;
            const unsigned* ad = (const unsigned*)&xd;
#pragma unroll
            for (int w = 0; w < 4; ++w) {
                // rmx values are nonnegative; hi halves compared with identical-class junk
                float m0 = fmax3(asf(au[w] << 16), asf(ac[w] << 16), asf(ad[w] << 16));
                float m1 = fmax3(asf(au[w] & 0xFFFF0000u), asf(ac[w] & 0xFFFF0000u), asf(ad[w] & 0xFFFF0000u));
                u64 m2 = mkf(m0, m1);
                pd2 = ffma2(m2, ctrabs[w], pd2);
                na2 = ffma2(m2, m2, na2);
            }
        }

        float pn = lohisum(pn2), cn = lohisum(cn2);
        float pd = lohisum(pd2), na = lohisum(na2);
        n1s[c] = cn;
        __syncthreads();

        float prior_n = fmaxf(sqrtf(pn), 1e-8f);
        float ssum = 0.f, smax = -INFINITY;
#pragma unroll
        for (int k = 0; k < 9; ++k) {
            float nn = fmaxf(sqrtf(n1s[nidx[k]]), 1e-8f);
            float s = __fdividef(lohisum(dot2[k]), prior_n * nn);
            if (pmask & (1u << k)) {
                ssum += s;
                smax = fmaxf(smax, s);
            }
        }
        float obj = (p0c > THRS && pmask) ? (-5.0f * smax + ssum) : 0.f;
        float nb = fmaxf(p1c * sqrtf(cn), 1e-6f);
        float cosp = __fdividef(pd * p1c, fmaxf(sqrtf(na), 1e-6f) * nb);
        float pool = -cosp * 0.5f * (p0c + p1c);

        wl = wsum(wl); pool = wsum(pool); obj = wsum(obj);
        if ((tid & 31) == 0) {
            atomicAdd(&rd[0], (double)wl);
            atomicAdd(&rd[1], (double)pool);
            atomicAdd(&rd[2], (double)obj);
        }
        __syncthreads();
        if (tid == 0) {
            atomicAdd(&g_slot[0][slot], rd[0]);
            atomicAdd(&g_slot[1][slot], rd[1]);
            atomicAdd(&g_slot[2][slot], rd[2]);
        }
    } else {
        // ================= image block: pres triples + flow term =================
        float* sp = (float*)smraw;
        int n = blk - npair;
        int t = n / B, b = n % B;
        int c = tid;

        float zpc = zp[(size_t)n * GG + c];
        sp[c] = zpc;
        __syncthreads();

        int i = c >> 4, j = c & 15;
        float mx = -INFINITY;
#pragma unroll
        for (int di = -1; di <= 1; ++di) {
            int ii = i + di;
            if (ii < 0 || ii >= G) continue;
#pragma unroll
            for (int dj = -1; dj <= 1; ++dj) {
                int jj = j + dj;
                if (jj < 0 || jj >= G) continue;
                mx = fmaxf(mx, sp[ii * G + jj]);
            }
        }

        float f = fl[(size_t)n * GG + c];
        float fsq = (f > 0.5f) ? (mx - f) * (mx - f) : 0.f;

        float pres = 0.f;
        if (t >= 1 && t <= TT - 2) {
            float za = zp[(size_t)(n - B) * GG + c];
            float zb = zp[(size_t)(n + B) * GG + c];
            float dba = zb - za;
            float sim = 1.f - dba * dba;
            float d1 = zb - zpc, d2 = za - zpc;
            pres += sim * (d1 * d1 + d2 * d2);
        }

        float v0 = wsum(fsq), v1 = wsum(zpc), v2 = wsum(f), v3 = wsum(pres);
        if ((c & 31) == 0) {
            atomicAdd(&rd[0], (double)v0);
            atomicAdd(&rd[1], (double)v1);
            atomicAdd(&rd[2], (double)v2);
            atomicAdd(&rd[3], (double)v3);
        }
        __syncthreads();
        if (tid == 0) {
            atomicAdd(&g_slot[4][slot], rd[0]);
            atomicAdd(&g_slot[5][slot], rd[1]);
            atomicAdd(&g_slot[6][slot], rd[2]);
            atomicAdd(&g_slot[3][slot], rd[3]);
        }
    }

    // ================= last-block finalize =================
    if (tid == 0) {
        __threadfence();
        unsigned old = atomicAdd(&g_ctr, 1u);
        isLast = (old == (unsigned)(npair + nimg) - 1u) ? 1u : 0u;
    }
    __syncthreads();

    if (isLast && tid == 0) {
        __threadfence();
        double acc[7];
#pragma unroll
        for (int q = 0; q < 7; ++q) {
            double s = 0.0;
#pragma unroll
            for (int r = 0; r < 16; ++r) { s += g_slot[q][r]; g_slot[q][r] = 0.0; }
            acc[q] = s;
        }
        g_ctr = 0u;

        int gi = *(const int*)gs;
        double gstep = (gi < 0 || gi > 1000000000) ? (double)__int_as_float(gi) : (double)gi;

        double scale_obj = gstep / 200000.0;        if (scale_obj > 1.0) scale_obj = 1.0;
        double scale_flow = 1.0 - gstep / 100000.0; if (scale_flow < 0.0) scale_flow = 0.0;

        double hinge = acc[5] - acc[6];
        if (hinge < 0.0) hinge = 0.0;
        double flow_loss = acc[4] + 100.0 * hinge;

        double loss = acc[0]                        // z_what_loss (ADJ_W=1)
                    + acc[3]                        // z_pres_loss (PRES_W=1)
                    + acc[1]                        // pool (POOL_W=1)
                    + acc[2] * scale_obj * 10.0     // objects * OBJ_W
                    + flow_loss * scale_flow;       // FLOW_W=1
        out[0] = (float)loss;
    }
}

extern "C" void kernel_launch(void* const* d_in, const int* in_sizes, int n_in,
                              void* d_out, int out_size) {
    const float* zw = (const float*)d_in[0];
    const float* zp = (const float*)d_in[1];
    const float* fl = (const float*)d_in[2];
    const void*  gs = d_in[3];
    int B = in_sizes[0] / (TT * GG * DD);

    static int configured = 0;
    if (!configured) {
        cudaFuncSetAttribute(fused_kernel, cudaFuncAttributeMaxDynamicSharedMemorySize, SMEM_BYTES);
        configured = 1;
    }

    int npair = (TT - 1) * B;
    int nimg  = TT * B;
    fused_kernel<<<npair + nimg, 256, SMEM_BYTES>>>(zw, zp, fl, gs, (float*)d_out, B, npair, nimg);
}

// round 6
// speedup vs baseline: 1.9446x; 1.0818x over previous
#include <cuda_runtime.h>
#include <cuda_bf16.h>

#define TT 8
#define G  16
#define GG 256
#define DD 64
#define THRS 0.5f

// slot-spread accumulators: 0 wl, 1 pool, 2 obj, 3 pres, 4 flowsq, 5 sumzp, 6 sumflow
__device__ double g_slot[7][16];
__device__ unsigned g_ctr;

typedef unsigned long long u64;

__device__ __forceinline__ float wsum(float v) {
#pragma unroll
    for (int s = 16; s > 0; s >>= 1) v += __shfl_xor_sync(0xffffffffu, v, s);
    return v;
}

// ---- packed f32x2 helpers ----
__device__ __forceinline__ u64 mk2(unsigned lo, unsigned hi) {
    u64 r; asm("mov.b64 %0, {%1, %2};" : "=l"(r) : "r"(lo), "r"(hi)); return r;
}
__device__ __forceinline__ u64 mkf(float lo, float hi) {
    u64 r; asm("mov.b64 %0, {%1, %2};" : "=l"(r) : "f"(lo), "f"(hi)); return r;
}
__device__ __forceinline__ u64 ffma2(u64 a, u64 b, u64 c) {
    u64 r; asm("fma.rn.f32x2 %0, %1, %2, %3;" : "=l"(r) : "l"(a), "l"(b), "l"(c)); return r;
}
__device__ __forceinline__ float lohisum(u64 v) {
    unsigned a, b; asm("mov.b64 {%0, %1}, %2;" : "=r"(a), "=r"(b) : "l"(v));
    return __uint_as_float(a) + __uint_as_float(b);
}

// ---- bf16 helpers (bf16 = top 16 bits of fp32) ----
__device__ __forceinline__ unsigned pk2(float e0, float e1) {
    unsigned r;
    asm("cvt.rn.bf16x2.f32 %0, %1, %2;" : "=r"(r) : "f"(e1), "f"(e0));
    return r;  // e0 low half, e1 high half
}
__device__ __forceinline__ unsigned mulbf2(unsigned a, unsigned b) {
    unsigned r; asm("mul.rn.bf16x2 %0, %1, %2;" : "=r"(r) : "r"(a), "r"(b)); return r;
}
__device__ __forceinline__ unsigned maxbf2(unsigned a, unsigned b) {
    unsigned r; asm("max.bf16x2 %0, %1, %2;" : "=r"(r) : "r"(a), "r"(b)); return r;
}

// XOR-swizzled uint4 index for a [GG][8]-uint4 frame: conflict-free, zero padding.
#define SWZ(cell, q) (((cell) << 3) + ((q) ^ ((cell) & 7)))

#define SMEM_BYTES (2 * GG * 8 * 16 + 3 * GG * 4)  // 68,608 B -> 3 blocks/SM

// blocks [0,npair): pair blocks (thread = cell); [npair,npair+nimg): image blocks.
__global__ __launch_bounds__(256, 3) void fused_kernel(const float* __restrict__ zw,
                                                       const float* __restrict__ zp,
                                                       const float* __restrict__ fl,
                                                       const void* __restrict__ gs,
                                                       float* __restrict__ out,
                                                       int B, int npair, int nimg) {
    extern __shared__ char smraw[];
    __shared__ double rd[4];
    __shared__ unsigned isLast;
    int tid = threadIdx.x;
    int blk = blockIdx.x;
    int slot = blk & 15;
    if (tid < 4) rd[tid] = 0.0;

    if (blk < npair) {
        // ================= pair block: wl / pool / objects =================
        uint4* s0b = (uint4*)smraw;            // frame t   bf16 [GG][8] swizzled
        uint4* s1b = s0b + GG * 8;             // frame t+1 bf16
        float* p0s = (float*)(s1b + GG * 8);
        float* p1s = p0s + GG;
        float* n1s = p1s + GG;

        int b = blk % B, t = blk / B;
        size_t f0 = (size_t)(t * B + b);
        size_t f1 = f0 + B;
        const float4* g0 = (const float4*)(zw + f0 * (GG * DD));
        const float4* g1 = (const float4*)(zw + f1 * (GG * DD));

        p0s[tid] = zp[f0 * GG + tid];
        p1s[tid] = zp[f1 * GG + tid];

        // coalesced load: exact fp32 z_what_loss (packed) + swizzled bf16 frames
        const u64 NEG1 = 0xBF800000BF800000ULL;  // {-1.f, -1.f}
        u64 wl2a = 0ULL, wl2b = 0ULL;
#pragma unroll
        for (int it = 0; it < 16; ++it) {
            int idx = it * 256 + tid;
            float4 a = g0[idx];
            float4 v = g1[idx];
            u64 a01 = mkf(a.x, a.y), a23 = mkf(a.z, a.w);
            u64 v01 = mkf(v.x, v.y), v23 = mkf(v.z, v.w);
            u64 d01 = ffma2(a01, NEG1, v01);
            u64 d23 = ffma2(a23, NEG1, v23);
            wl2a = ffma2(d01, d01, wl2a);
            wl2b = ffma2(d23, d23, wl2b);
            int cell = idx >> 4, d4 = idx & 15;
            int q = d4 >> 1, h = d4 & 1;
            int u2idx = SWZ(cell, q) * 2 + h;
            uint2 pa, pb;
            pa.x = pk2(a.x, a.y);  pa.y = pk2(a.z, a.w);
            pb.x = pk2(v.x, v.y);  pb.y = pk2(v.z, v.w);
            ((uint2*)s0b)[u2idx] = pa;
            ((uint2*)s1b)[u2idx] = pb;
        }
        float wl = lohisum(wl2a) + lohisum(wl2b);
        __syncthreads();

        int c = tid;
        int i = c >> 4, j = c & 15;
        float p0c = p0s[c], p1c = p1s[c];

        // wrapped neighbor indexing (objects term, frame t+1) + pres mask
        int nb8[9], n7[9];
        unsigned pmask = 0;
        {
            int k = 0;
#pragma unroll
            for (int di = -1; di <= 1; ++di)
#pragma unroll
                for (int dj = -1; dj <= 1; ++dj, ++k) {
                    int nc = ((i + di) & 15) * 16 + ((j + dj) & 15);
                    nb8[k] = nc << 3;
                    n7[k] = nc & 7;
                    if (p1s[nc] > THRS) pmask |= (1u << k);
                }
        }

        // ---- loop A: prior norm + 9 wrapped dots ----
        u64 dot2[9];
#pragma unroll
        for (int k = 0; k < 9; ++k) dot2[k] = 0ULL;
        u64 pn2 = 0ULL;
        int cb = c << 3, cx = c & 7;
#pragma unroll
        for (int q = 0; q < 8; ++q) {
            uint4 pu = s0b[cb + (q ^ cx)];
            const unsigned* pw = (const unsigned*)&pu;
            u64 pr2[4];
#pragma unroll
            for (int w = 0; w < 4; ++w) {
                pr2[w] = mk2(pw[w] << 16, pw[w] & 0xFFFF0000u);   // exact pair
                pn2 = ffma2(pr2[w], pr2[w], pn2);
            }
#pragma unroll
            for (int k = 0; k < 9; ++k) {
                uint4 nu = s1b[nb8[k] + (q ^ n7[k])];
                const unsigned* nw = (const unsigned*)&nu;
#pragma unroll
                for (int w = 0; w < 4; ++w) {
                    // hi half carries <=2^-8 mantissa junk: benign
                    dot2[k] = ffma2(pr2[w], mk2(nw[w] << 16, nw[w]), dot2[k]);
                }
            }
        }
        float dotf[9];
#pragma unroll
        for (int k = 0; k < 9; ++k) dotf[k] = lohisum(dot2[k]);
        float pn = lohisum(pn2);

        // clamped pool indexing (maxpool term, frame t): pz=0 for out-of-grid
        int cb8[9], c7[9];
        unsigned pzb[9];
        {
            int k = 0;
#pragma unroll
            for (int di = -1; di <= 1; ++di)
#pragma unroll
                for (int dj = -1; dj <= 1; ++dj, ++k) {
                    int ii = i + di, jj = j + dj;
                    bool inb = (ii >= 0 && ii < G && jj >= 0 && jj < G);
                    int ci = inb ? ii : i, cj = inb ? jj : j;
                    int pc = ci * 16 + cj;
                    cb8[k] = pc << 3;
                    c7[k] = pc & 7;
                    float pz = inb ? p0s[pc] : 0.f;
                    pzb[k] = pk2(pz, pz);
                }
        }

        // ---- loop B: fused 3x3 maxpool (bf16x2) + pool-cos partials ----
        u64 cn2 = 0ULL, pd2 = 0ULL, na2 = 0ULL;
#pragma unroll
        for (int q = 0; q < 8; ++q) {
            uint4 cu = s1b[cb + (q ^ cx)];
            const unsigned* cw = (const unsigned*)&cu;
            u64 ctrabs[4];
#pragma unroll
            for (int w = 0; w < 4; ++w) {
                ctrabs[w] = mk2((cw[w] << 16) & 0x7FFF0000u, cw[w] & 0x7FFF0000u);
                cn2 = ffma2(ctrabs[w], ctrabs[w], cn2);
            }
            unsigned mb[4] = {0u, 0u, 0u, 0u};
#pragma unroll
            for (int k = 0; k < 9; ++k) {
                uint4 su = s0b[cb8[k] + (q ^ c7[k])];
                const unsigned* sw = (const unsigned*)&su;
#pragma unroll
                for (int w = 0; w < 4; ++w) {
                    unsigned prod = mulbf2(sw[w] & 0x7FFF7FFFu, pzb[k]);
                    mb[w] = maxbf2(mb[w], prod);
                }
            }
#pragma unroll
            for (int w = 0; w < 4; ++w) {
                u64 m2 = mk2(mb[w] << 16, mb[w] & 0xFFFF0000u);
                pd2 = ffma2(m2, ctrabs[w], pd2);
                na2 = ffma2(m2, m2, na2);
            }
        }
        float cn = lohisum(cn2), pd = lohisum(pd2), na = lohisum(na2);

        n1s[c] = cn;     // ||frame-(t+1) cell||^2, consumed by the 8 neighbors
        __syncthreads();

        float prior_n = fmaxf(sqrtf(pn), 1e-8f);
        float ssum = 0.f, smax = -INFINITY;
#pragma unroll
        for (int k = 0; k < 9; ++k) {
            float nn = fmaxf(sqrtf(n1s[nb8[k] >> 3]), 1e-8f);
            float s = __fdividef(dotf[k], prior_n * nn);
            if (pmask & (1u << k)) {
                ssum += s;
                smax = fmaxf(smax, s);
            }
        }
        float obj = (p0c > THRS && pmask) ? (-5.0f * smax + ssum) : 0.f;
        float nb = fmaxf(p1c * sqrtf(cn), 1e-6f);
        float cosp = __fdividef(pd * p1c, fmaxf(sqrtf(na), 1e-6f) * nb);
        float pool = -cosp * 0.5f * (p0c + p1c);

        wl = wsum(wl); pool = wsum(pool); obj = wsum(obj);
        if ((tid & 31) == 0) {
            atomicAdd(&rd[0], (double)wl);
            atomicAdd(&rd[1], (double)pool);
            atomicAdd(&rd[2], (double)obj);
        }
        __syncthreads();
        if (tid == 0) {
            atomicAdd(&g_slot[0][slot], rd[0]);
            atomicAdd(&g_slot[1][slot], rd[1]);
            atomicAdd(&g_slot[2][slot], rd[2]);
        }
    } else {
        // ================= image block: pres triples + flow term =================
        float* sp = (float*)smraw;
        int n = blk - npair;
        int t = n / B, b = n % B;
        int c = tid;

        float zpc = zp[(size_t)n * GG + c];
        sp[c] = zpc;
        __syncthreads();

        int i = c >> 4, j = c & 15;
        float mx = -INFINITY;
#pragma unroll
        for (int di = -1; di <= 1; ++di) {
            int ii = i + di;
            if (ii < 0 || ii >= G) continue;
#pragma unroll
            for (int dj = -1; dj <= 1; ++dj) {
                int jj = j + dj;
                if (jj < 0 || jj >= G) continue;
                mx = fmaxf(mx, sp[ii * G + jj]);
            }
        }

        float f = fl[(size_t)n * GG + c];
        float fsq = (f > 0.5f) ? (mx - f) * (mx - f) : 0.f;

        float pres = 0.f;
        if (t >= 1 && t <= TT - 2) {
            float za = zp[(size_t)(n - B) * GG + c];
            float zb = zp[(size_t)(n + B) * GG + c];
            float dba = zb - za;
            float sim = 1.f - dba * dba;
            float d1 = zb - zpc, d2 = za - zpc;
            pres += sim * (d1 * d1 + d2 * d2);
        }

        float v0 = wsum(fsq), v1 = wsum(zpc), v2 = wsum(f), v3 = wsum(pres);
        if ((c & 31) == 0) {
            atomicAdd(&rd[0], (double)v0);
            atomicAdd(&rd[1], (double)v1);
            atomicAdd(&rd[2], (double)v2);
            atomicAdd(&rd[3], (double)v3);
        }
        __syncthreads();
        if (tid == 0) {
            atomicAdd(&g_slot[4][slot], rd[0]);
            atomicAdd(&g_slot[5][slot], rd[1]);
            atomicAdd(&g_slot[6][slot], rd[2]);
            atomicAdd(&g_slot[3][slot], rd[3]);
        }
    }

    // ================= last-block finalize =================
    if (tid == 0) {
        __threadfence();
        unsigned old = atomicAdd(&g_ctr, 1u);
        isLast = (old == (unsigned)(npair + nimg) - 1u) ? 1u : 0u;
    }
    __syncthreads();

    if (isLast && tid == 0) {
        __threadfence();
        double acc[7];
#pragma unroll
        for (int q = 0; q < 7; ++q) {
            double s = 0.0;
#pragma unroll
            for (int r = 0; r < 16; ++r) { s += g_slot[q][r]; g_slot[q][r] = 0.0; }
            acc[q] = s;
        }
        g_ctr = 0u;

        int gi = *(const int*)gs;
        double gstep = (gi < 0 || gi > 1000000000) ? (double)__int_as_float(gi) : (double)gi;

        double scale_obj = gstep / 200000.0;        if (scale_obj > 1.0) scale_obj = 1.0;
        double scale_flow = 1.0 - gstep / 100000.0; if (scale_flow < 0.0) scale_flow = 0.0;

        double hinge = acc[5] - acc[6];
        if (hinge < 0.0) hinge = 0.0;
        double flow_loss = acc[4] + 100.0 * hinge;

        double loss = acc[0]                        // z_what_loss (ADJ_W=1)
                    + acc[3]                        // z_pres_loss (PRES_W=1)
                    + acc[1]                        // pool (POOL_W=1)
                    + acc[2] * scale_obj * 10.0     // objects * OBJ_W
                    + flow_loss * scale_flow;       // FLOW_W=1
        out[0] = (float)loss;
    }
}

extern "C" void kernel_launch(void* const* d_in, const int* in_sizes, int n_in,
                              void* d_out, int out_size) {
    const float* zw = (const float*)d_in[0];
    const float* zp = (const float*)d_in[1];
    const float* fl = (const float*)d_in[2];
    const void*  gs = d_in[3];
    int B = in_sizes[0] / (TT * GG * DD);

    static int configured = 0;
    if (!configured) {
        cudaFuncSetAttribute(fused_kernel, cudaFuncAttributeMaxDynamicSharedMemorySize, SMEM_BYTES);
        configured = 1;
    }

    int npair = (TT - 1) * B;
    int nimg  = TT * B;
    fused_kernel<<<npair + nimg, 256, SMEM_BYTES>>>(zw, zp, fl, gs, (float*)d_out, B, npair, nimg);
}